// round 7
// baseline (speedup 1.0000x reference)
#include <cuda_runtime.h>
#include <cstddef>

// Problem constants
#define N_SEQ   64
#define L_SEQ   512
#define D_IN    1280
#define M_ROWS  (N_SEQ * L_SEQ)     // 32768 (n,l) rows
#define COLS    36                   // 32 proj outputs + 1 token col + 3 pad
#define N_TILES 8                    // 512 / 64
#define N_PAIRS 36                   // upper-tri tile pairs (lb <= mb)
#define SCALE_CONST 0.08838834764831845f  // 1/(4*sqrt(8))

// Scratch (static device globals: no allocation in kernel_launch)
__device__ float g_W[COLS * D_IN];          // [36][1280] concat weight
__device__ float g_h[M_ROWS * 32];          // projected h, [32768][32]
__device__ float g_t[M_ROWS];               // token-linear per (n,l)
__device__ float g_partial[N_SEQ * N_PAIRS];// per-tile second-order partials

// ---- packed fp32x2 helpers (sm_100+ only; ptxas will not auto-fuse) ----
__device__ __forceinline__ void fma2(unsigned long long &d,
                                     unsigned long long a,
                                     unsigned long long b) {
    asm("fma.rn.f32x2 %0, %1, %2, %0;" : "+l"(d) : "l"(a), "l"(b));
}
__device__ __forceinline__ float hsum2(unsigned long long u) {
    float lo, hi;
    asm("mov.b64 {%0, %1}, %2;" : "=f"(lo), "=f"(hi) : "l"(u));
    return lo + hi;
}

// ---------------------------------------------------------------------------
// K0: build concatenated weight matrix g_W: rows 0..31 = W_proj, row 32 =
//     w_token, rows 33..35 = 0. Idempotent (re-run every launch).
// ---------------------------------------------------------------------------
__global__ void build_w_kernel(const float* __restrict__ W_proj,
                               const float* __restrict__ w_token) {
    int i = blockIdx.x * blockDim.x + threadIdx.x;
    if (i < COLS * D_IN) {
        int k = i / D_IN;
        int d = i - k * D_IN;
        float v = 0.0f;
        if (k < 32)       v = W_proj[i];
        else if (k == 32) v = w_token[d];
        g_W[i] = v;
    }
}

// ---------------------------------------------------------------------------
// K1: projection GEMM. C[32768, 36] = x[32768,1280] @ g_W^T.
// Block: 192 threads (6 warps), tile 128 rows x 36 cols, K-chunks of 32.
// Grid = 256 blocks -> single full-chip wave at occ 2 (296 slots >= 256).
// Thread micro-tile: 4 rows (strided by 32) x 6 cols, f32x2 packed along K.
// 2-stage register prefetch; epilogue staged via smem for coalesced STG.128.
// ---------------------------------------------------------------------------
#define KC        32
#define KPAD      38          // >=36 output cols; 2*19 -> conflict-free LDS.64
#define TILE_ROWS 128
#define K1_THREADS 192
#define NF4_X     (TILE_ROWS * KC / 4)          // 1024 float4 per x chunk
#define NF4_TOT   (NF4_X + COLS * KC / 4)       // + 288 = 1312 total
#define NLD       7                              // ceil(1312/192)

__global__ __launch_bounds__(K1_THREADS, 2)
void proj_kernel(const float* __restrict__ x) {
    __shared__ float xs[TILE_ROWS][KPAD];
    __shared__ float ws[COLS][KPAD];

    const int tid  = threadIdx.x;
    const int warp = tid >> 5;      // 0..5 -> column group
    const int lane = tid & 31;      // row within stride group
    const int rowbase = blockIdx.x * TILE_ROWS;

    unsigned long long acc[4][6];
#pragma unroll
    for (int i = 0; i < 4; i++)
#pragma unroll
        for (int j = 0; j < 6; j++) acc[i][j] = 0ULL;

    float4 buf[NLD];

    auto load_chunk = [&](int kb) {
#pragma unroll
        for (int it = 0; it < NLD; it++) {
            int i = tid + it * K1_THREADS;
            if (i < NF4_TOT) {
                if (i < NF4_X) {
                    int r  = i >> 3;
                    int k4 = (i & 7) << 2;
                    buf[it] = *(const float4*)(x + (size_t)(rowbase + r) * D_IN + kb + k4);
                } else {
                    int j  = i - NF4_X;
                    int r  = j >> 3;
                    int k4 = (j & 7) << 2;
                    buf[it] = *(const float4*)(g_W + r * D_IN + kb + k4);
                }
            }
        }
    };
    auto store_chunk = [&]() {
#pragma unroll
        for (int it = 0; it < NLD; it++) {
            int i = tid + it * K1_THREADS;
            if (i < NF4_TOT) {
                float4 v = buf[it];
                if (i < NF4_X) {
                    int r  = i >> 3;
                    int k4 = (i & 7) << 2;
                    *(float2*)&xs[r][k4]     = make_float2(v.x, v.y);
                    *(float2*)&xs[r][k4 + 2] = make_float2(v.z, v.w);
                } else {
                    int j  = i - NF4_X;
                    int r  = j >> 3;
                    int k4 = (j & 7) << 2;
                    *(float2*)&ws[r][k4]     = make_float2(v.x, v.y);
                    *(float2*)&ws[r][k4 + 2] = make_float2(v.z, v.w);
                }
            }
        }
    };

    load_chunk(0);

    const int NCHUNK = D_IN / KC;   // 40
    for (int c = 0; c < NCHUNK; c++) {
        store_chunk();
        __syncthreads();

        if (c + 1 < NCHUNK)
            load_chunk((c + 1) * KC);   // LDGs fly during compute below

#pragma unroll 4
        for (int k2 = 0; k2 < KC / 2; k2++) {
            unsigned long long xv[4], wv[6];
#pragma unroll
            for (int i = 0; i < 4; i++)
                xv[i] = *(const unsigned long long*)&xs[lane + (i << 5)][k2 * 2];
#pragma unroll
            for (int j = 0; j < 6; j++)
                wv[j] = *(const unsigned long long*)&ws[warp * 6 + j][k2 * 2];
#pragma unroll
            for (int i = 0; i < 4; i++)
#pragma unroll
                for (int j = 0; j < 6; j++)
                    fma2(acc[i][j], xv[i], wv[j]);
        }
        __syncthreads();
    }

    // epilogue: stage results in smem (xs reusable after last barrier),
    // then fully coalesced STG.128 writeout.
#pragma unroll
    for (int i = 0; i < 4; i++) {
        int r = lane + (i << 5);
#pragma unroll
        for (int j = 0; j < 6; j++)
            xs[r][warp * 6 + j] = hsum2(acc[i][j]);
    }
    __syncthreads();

    for (int i = tid; i < TILE_ROWS * 8; i += K1_THREADS) {
        int r = i >> 3;
        int q = (i & 7) << 2;
        float4 v = make_float4(xs[r][q], xs[r][q + 1], xs[r][q + 2], xs[r][q + 3]);
        *(float4*)(g_h + (size_t)(rowbase + r) * 32 + q) = v;
    }
    for (int r = tid; r < TILE_ROWS; r += K1_THREADS)
        g_t[rowbase + r] = xs[r][32];
}

// ---------------------------------------------------------------------------
// K2: second-order. For tile pair (lb<=mb) of sequence positions, compute
// G = Hl @ Hm^T (64x64, K=32), multiply by priors with strict upper mask,
// reduce to a deterministic per-block partial.
// ---------------------------------------------------------------------------
#define HPAD 34

__global__ __launch_bounds__(256)
void attn_kernel(const float* __restrict__ priors) {
    __shared__ float hl[64][HPAD];
    __shared__ float hm[64][HPAD];
    __shared__ float red[8];

    const int bx = blockIdx.x;
    const int n  = bx / N_PAIRS;
    const int tp = bx - n * N_PAIRS;

    // decode upper-tri tile pair
    int lb = 0, rem = tp;
#pragma unroll
    for (int q = 0; q < N_TILES; q++) {
        int cnt = N_TILES - q;
        if (rem < cnt) { lb = q; break; }
        rem -= cnt;
    }
    const int mb = lb + rem;

    const int tid = threadIdx.x;
    const float* Hl = g_h + (size_t)(n * L_SEQ + lb * 64) * 32;
    const float* Hm = g_h + (size_t)(n * L_SEQ + mb * 64) * 32;

    // load both 64x32 H tiles (512 float4 each)
    for (int i = tid; i < 512; i += 256) {
        int r  = i >> 3;
        int k4 = (i & 7) << 2;
        float4 v = *(const float4*)(Hl + r * 32 + k4);
        *(float2*)&hl[r][k4]     = make_float2(v.x, v.y);
        *(float2*)&hl[r][k4 + 2] = make_float2(v.z, v.w);
        float4 u = *(const float4*)(Hm + r * 32 + k4);
        *(float2*)&hm[r][k4]     = make_float2(u.x, u.y);
        *(float2*)&hm[r][k4 + 2] = make_float2(u.z, u.w);
    }
    __syncthreads();

    const int lg = tid >> 4;   // 0..15
    const int mg = tid & 15;   // 0..15

    unsigned long long acc[4][4];
#pragma unroll
    for (int i = 0; i < 4; i++)
#pragma unroll
        for (int j = 0; j < 4; j++) acc[i][j] = 0ULL;

#pragma unroll 4
    for (int k2 = 0; k2 < 16; k2++) {
        unsigned long long a[4], b[4];
#pragma unroll
        for (int i = 0; i < 4; i++)
            a[i] = *(const unsigned long long*)&hl[lg + (i << 4)][k2 * 2];
#pragma unroll
        for (int j = 0; j < 4; j++)
            b[j] = *(const unsigned long long*)&hm[mg + (j << 4)][k2 * 2];
#pragma unroll
        for (int i = 0; i < 4; i++)
#pragma unroll
            for (int j = 0; j < 4; j++)
                fma2(acc[i][j], a[i], b[j]);
    }

    // apply priors with strict upper-tri mask, accumulate
    float partial = 0.0f;
    const float* P = priors + (size_t)n * L_SEQ * L_SEQ;
#pragma unroll
    for (int i = 0; i < 4; i++) {
        int l = lb * 64 + lg + (i << 4);
#pragma unroll
        for (int j = 0; j < 4; j++) {
            int m = mb * 64 + mg + (j << 4);
            if (m > l)
                partial += hsum2(acc[i][j]) * __ldg(&P[(size_t)l * L_SEQ + m]);
        }
    }

    // deterministic block reduce
#pragma unroll
    for (int off = 16; off; off >>= 1)
        partial += __shfl_down_sync(0xffffffffu, partial, off);
    if ((tid & 31) == 0) red[tid >> 5] = partial;
    __syncthreads();
    if (tid == 0) {
        float s = 0.0f;
#pragma unroll
        for (int w = 0; w < 8; w++) s += red[w];
        g_partial[bx] = s;
    }
}

// ---------------------------------------------------------------------------
// K3: finalize. out[n] = (sum_l t[n,l]*w_seq[l]) + b + scale*IS*second[n]
// ---------------------------------------------------------------------------
__global__ __launch_bounds__(128)
void final_kernel(const float* __restrict__ w_seq,
                  const float* __restrict__ b_seq,
                  const float* __restrict__ iscale,
                  float* __restrict__ out) {
    const int n   = blockIdx.x;
    const int tid = threadIdx.x;
    __shared__ float red[128];

    float s = 0.0f;
    for (int l = tid; l < L_SEQ; l += 128)
        s += g_t[n * L_SEQ + l] * w_seq[l];

    float sc = SCALE_CONST * iscale[0];
    if (tid < N_PAIRS)
        s += sc * g_partial[n * N_PAIRS + tid];

    red[tid] = s;
    __syncthreads();
#pragma unroll
    for (int off = 64; off; off >>= 1) {
        if (tid < off) red[tid] += red[tid + off];
        __syncthreads();
    }
    if (tid == 0) out[n] = red[0] + b_seq[0];
}

// ---------------------------------------------------------------------------
extern "C" void kernel_launch(void* const* d_in, const int* in_sizes, int n_in,
                              void* d_out, int out_size) {
    const float* x        = (const float*)d_in[0];  // (64,512,1280)
    const float* priors   = (const float*)d_in[1];  // (64,512,512)
    const float* w_token  = (const float*)d_in[2];  // (1280)
    const float* w_seq    = (const float*)d_in[3];  // (512)
    const float* b_seq    = (const float*)d_in[4];  // scalar
    const float* W_proj   = (const float*)d_in[5];  // (32,1280)
    const float* iscale   = (const float*)d_in[6];  // scalar
    float* out = (float*)d_out;                     // (64)

    build_w_kernel<<<(COLS * D_IN + 255) / 256, 256>>>(W_proj, w_token);
    proj_kernel<<<M_ROWS / TILE_ROWS, K1_THREADS>>>(x);
    attn_kernel<<<N_SEQ * N_PAIRS, 256>>>(priors);
    final_kernel<<<N_SEQ, 128>>>(w_seq, b_seq, iscale, out);
}

// round 8
// speedup vs baseline: 1.0215x; 1.0215x over previous
#include <cuda_runtime.h>
#include <cstddef>

// Problem constants
#define N_SEQ   64
#define L_SEQ   512
#define D_IN    1280
#define M_ROWS  (N_SEQ * L_SEQ)     // 32768 (n,l) rows
#define COLS    36                   // 32 proj outputs + 1 token col + 3 pad
#define N_TILES 8                    // 512 / 64
#define N_PAIRS 36                   // upper-tri tile pairs (lb <= mb)
#define SCALE_CONST 0.08838834764831845f  // 1/(4*sqrt(8))

// Scratch (static device globals: no allocation in kernel_launch)
__device__ float g_h[M_ROWS * 32];          // projected h, [32768][32]
__device__ float g_fo[M_ROWS / 128];        // per-block first-order partials (256)
__device__ float g_partial[N_SEQ * N_PAIRS];// per-tile second-order partials

// ---- packed fp32x2 helpers (sm_100+ only; ptxas will not auto-fuse) ----
__device__ __forceinline__ void fma2(unsigned long long &d,
                                     unsigned long long a,
                                     unsigned long long b) {
    asm("fma.rn.f32x2 %0, %1, %2, %0;" : "+l"(d) : "l"(a), "l"(b));
}
__device__ __forceinline__ float hsum2(unsigned long long u) {
    float lo, hi;
    asm("mov.b64 {%0, %1}, %2;" : "=f"(lo), "=f"(hi) : "l"(u));
    return lo + hi;
}

// ---------------------------------------------------------------------------
// K1: projection GEMM. C[32768, 36] = x[32768,1280] @ [W_proj; w_token; 0]^T.
// Block: 192 threads (6 warps), tile 128 rows x 36 cols, K-chunks of 32.
// Grid = 256 blocks -> single full-chip wave at occ 2.
// Thread micro-tile: 4 rows (strided by 32) x 6 cols, f32x2 packed along K.
// 2-stage register prefetch; W loaded straight from inputs (no staging pass).
// Epilogue: smem-staged coalesced STG.128 of h + per-block first-order dot.
// ---------------------------------------------------------------------------
#define KC        32
#define KPAD      38          // >=36 output cols; stride 19 pairs, gcd(19,16)=1
#define TILE_ROWS 128
#define K1_THREADS 192
#define NF4_X     (TILE_ROWS * KC / 4)          // 1024 float4 per x chunk
#define NF4_TOT   (NF4_X + COLS * KC / 4)       // + 288 = 1312 total
#define NLD       7                              // ceil(1312/192)

__global__ __launch_bounds__(K1_THREADS, 2)
void proj_kernel(const float* __restrict__ x,
                 const float* __restrict__ W_proj,
                 const float* __restrict__ w_token,
                 const float* __restrict__ w_seq) {
    __shared__ float xs[TILE_ROWS][KPAD];
    __shared__ float ws[COLS][KPAD];
    __shared__ float fored[6];

    const int tid  = threadIdx.x;
    const int warp = tid >> 5;      // 0..5 -> column group
    const int lane = tid & 31;      // row within stride group
    const int rowbase = blockIdx.x * TILE_ROWS;

    unsigned long long acc[4][6];
#pragma unroll
    for (int i = 0; i < 4; i++)
#pragma unroll
        for (int j = 0; j < 6; j++) acc[i][j] = 0ULL;

    float4 buf[NLD];

    auto load_chunk = [&](int kb) {
#pragma unroll
        for (int it = 0; it < NLD; it++) {
            int i = tid + it * K1_THREADS;
            if (i < NF4_TOT) {
                if (i < NF4_X) {
                    int r  = i >> 3;
                    int k4 = (i & 7) << 2;
                    buf[it] = *(const float4*)(x + (size_t)(rowbase + r) * D_IN + kb + k4);
                } else {
                    int j  = i - NF4_X;
                    int r  = j >> 3;             // 0..35
                    int k4 = (j & 7) << 2;
                    if (r < 32)
                        buf[it] = *(const float4*)(W_proj + (size_t)r * D_IN + kb + k4);
                    else if (r == 32)
                        buf[it] = *(const float4*)(w_token + kb + k4);
                    else
                        buf[it] = make_float4(0.f, 0.f, 0.f, 0.f);
                }
            }
        }
    };
    auto store_chunk = [&]() {
#pragma unroll
        for (int it = 0; it < NLD; it++) {
            int i = tid + it * K1_THREADS;
            if (i < NF4_TOT) {
                float4 v = buf[it];
                if (i < NF4_X) {
                    int r  = i >> 3;
                    int k4 = (i & 7) << 2;
                    *(float2*)&xs[r][k4]     = make_float2(v.x, v.y);
                    *(float2*)&xs[r][k4 + 2] = make_float2(v.z, v.w);
                } else {
                    int j  = i - NF4_X;
                    int r  = j >> 3;
                    int k4 = (j & 7) << 2;
                    *(float2*)&ws[r][k4]     = make_float2(v.x, v.y);
                    *(float2*)&ws[r][k4 + 2] = make_float2(v.z, v.w);
                }
            }
        }
    };

    load_chunk(0);

    const int NCHUNK = D_IN / KC;   // 40
    for (int c = 0; c < NCHUNK; c++) {
        store_chunk();
        __syncthreads();

        if (c + 1 < NCHUNK)
            load_chunk((c + 1) * KC);   // LDGs fly during compute below

#pragma unroll 4
        for (int k2 = 0; k2 < KC / 2; k2++) {
            unsigned long long xv[4], wv[6];
#pragma unroll
            for (int i = 0; i < 4; i++)
                xv[i] = *(const unsigned long long*)&xs[lane + (i << 5)][k2 * 2];
#pragma unroll
            for (int j = 0; j < 6; j++)
                wv[j] = *(const unsigned long long*)&ws[warp * 6 + j][k2 * 2];
#pragma unroll
            for (int i = 0; i < 4; i++)
#pragma unroll
                for (int j = 0; j < 6; j++)
                    fma2(acc[i][j], xv[i], wv[j]);
        }
        __syncthreads();
    }

    // epilogue: stage results in smem (xs reusable after last barrier),
    // then fully coalesced STG.128 writeout + first-order block partial.
#pragma unroll
    for (int i = 0; i < 4; i++) {
        int r = lane + (i << 5);
#pragma unroll
        for (int j = 0; j < 6; j++)
            xs[r][warp * 6 + j] = hsum2(acc[i][j]);
    }
    __syncthreads();

    for (int i = tid; i < TILE_ROWS * 8; i += K1_THREADS) {
        int r = i >> 3;
        int q = (i & 7) << 2;
        float4 v = make_float4(xs[r][q], xs[r][q + 1], xs[r][q + 2], xs[r][q + 3]);
        *(float4*)(g_h + (size_t)(rowbase + r) * 32 + q) = v;
    }

    // first-order partial: rows of this block are l = l0 + r within one n.
    {
        const int l0 = rowbase & (L_SEQ - 1);
        float fo = (tid < TILE_ROWS) ? xs[tid][32] * w_seq[l0 + tid] : 0.0f;
#pragma unroll
        for (int off = 16; off; off >>= 1)
            fo += __shfl_down_sync(0xffffffffu, fo, off);
        if (lane == 0) fored[warp] = fo;
        __syncthreads();
        if (tid == 0) {
            float s = 0.0f;
#pragma unroll
            for (int w = 0; w < 6; w++) s += fored[w];
            g_fo[blockIdx.x] = s;
        }
    }
}

// ---------------------------------------------------------------------------
// K2: second-order. For tile pair (lb<=mb) of sequence positions, compute
// G = Hl @ Hm^T (64x64, K=32), multiply by priors with strict upper mask,
// reduce to a deterministic per-block partial.
// ---------------------------------------------------------------------------
#define HPAD 34

__global__ __launch_bounds__(256)
void attn_kernel(const float* __restrict__ priors) {
    __shared__ float hl[64][HPAD];
    __shared__ float hm[64][HPAD];
    __shared__ float red[8];

    const int bx = blockIdx.x;
    const int n  = bx / N_PAIRS;
    const int tp = bx - n * N_PAIRS;

    // decode upper-tri tile pair
    int lb = 0, rem = tp;
#pragma unroll
    for (int q = 0; q < N_TILES; q++) {
        int cnt = N_TILES - q;
        if (rem < cnt) { lb = q; break; }
        rem -= cnt;
    }
    const int mb = lb + rem;

    const int tid = threadIdx.x;
    const float* Hl = g_h + (size_t)(n * L_SEQ + lb * 64) * 32;
    const float* Hm = g_h + (size_t)(n * L_SEQ + mb * 64) * 32;

    // load both 64x32 H tiles (512 float4 each)
    for (int i = tid; i < 512; i += 256) {
        int r  = i >> 3;
        int k4 = (i & 7) << 2;
        float4 v = *(const float4*)(Hl + r * 32 + k4);
        *(float2*)&hl[r][k4]     = make_float2(v.x, v.y);
        *(float2*)&hl[r][k4 + 2] = make_float2(v.z, v.w);
        float4 u = *(const float4*)(Hm + r * 32 + k4);
        *(float2*)&hm[r][k4]     = make_float2(u.x, u.y);
        *(float2*)&hm[r][k4 + 2] = make_float2(u.z, u.w);
    }
    __syncthreads();

    const int lg = tid >> 4;   // 0..15
    const int mg = tid & 15;   // 0..15

    unsigned long long acc[4][4];
#pragma unroll
    for (int i = 0; i < 4; i++)
#pragma unroll
        for (int j = 0; j < 4; j++) acc[i][j] = 0ULL;

#pragma unroll 4
    for (int k2 = 0; k2 < 16; k2++) {
        unsigned long long a[4], b[4];
#pragma unroll
        for (int i = 0; i < 4; i++)
            a[i] = *(const unsigned long long*)&hl[lg + (i << 4)][k2 * 2];
#pragma unroll
        for (int j = 0; j < 4; j++)
            b[j] = *(const unsigned long long*)&hm[mg + (j << 4)][k2 * 2];
#pragma unroll
        for (int i = 0; i < 4; i++)
#pragma unroll
            for (int j = 0; j < 4; j++)
                fma2(acc[i][j], a[i], b[j]);
    }

    // apply priors with strict upper-tri mask, accumulate
    float partial = 0.0f;
    const float* P = priors + (size_t)n * L_SEQ * L_SEQ;
#pragma unroll
    for (int i = 0; i < 4; i++) {
        int l = lb * 64 + lg + (i << 4);
#pragma unroll
        for (int j = 0; j < 4; j++) {
            int m = mb * 64 + mg + (j << 4);
            if (m > l)
                partial += hsum2(acc[i][j]) * __ldg(&P[(size_t)l * L_SEQ + m]);
        }
    }

    // deterministic block reduce
#pragma unroll
    for (int off = 16; off; off >>= 1)
        partial += __shfl_down_sync(0xffffffffu, partial, off);
    if ((tid & 31) == 0) red[tid >> 5] = partial;
    __syncthreads();
    if (tid == 0) {
        float s = 0.0f;
#pragma unroll
        for (int w = 0; w < 8; w++) s += red[w];
        g_partial[bx] = s;
    }
}

// ---------------------------------------------------------------------------
// K3: finalize. out[n] = sum(4 fo partials) + b + scale*IS*sum(36 partials)
// ---------------------------------------------------------------------------
__global__ __launch_bounds__(64)
void final_kernel(const float* __restrict__ b_seq,
                  const float* __restrict__ iscale,
                  float* __restrict__ out) {
    const int n   = blockIdx.x;
    const int tid = threadIdx.x;
    __shared__ float red[2];

    const float sc = SCALE_CONST * iscale[0];
    float s = 0.0f;
    if (tid < 4)       s += g_fo[n * 4 + tid];
    if (tid < N_PAIRS) s += sc * g_partial[n * N_PAIRS + tid];

#pragma unroll
    for (int off = 16; off; off >>= 1)
        s += __shfl_down_sync(0xffffffffu, s, off);
    if ((tid & 31) == 0) red[tid >> 5] = s;
    __syncthreads();
    if (tid == 0) out[n] = red[0] + red[1] + b_seq[0];
}

// ---------------------------------------------------------------------------
extern "C" void kernel_launch(void* const* d_in, const int* in_sizes, int n_in,
                              void* d_out, int out_size) {
    const float* x        = (const float*)d_in[0];  // (64,512,1280)
    const float* priors   = (const float*)d_in[1];  // (64,512,512)
    const float* w_token  = (const float*)d_in[2];  // (1280)
    const float* w_seq    = (const float*)d_in[3];  // (512)
    const float* b_seq    = (const float*)d_in[4];  // scalar
    const float* W_proj   = (const float*)d_in[5];  // (32,1280)
    const float* iscale   = (const float*)d_in[6];  // scalar
    float* out = (float*)d_out;                     // (64)

    proj_kernel<<<M_ROWS / TILE_ROWS, K1_THREADS>>>(x, W_proj, w_token, w_seq);
    attn_kernel<<<N_SEQ * N_PAIRS, 256>>>(priors);
    final_kernel<<<N_SEQ, 64>>>(b_seq, iscale, out);
}